// round 5
// baseline (speedup 1.0000x reference)
#include <cuda_runtime.h>
#include <cstdint>

// Problem constants
#define BATCH 4
#define CH    64
#define HH    64
#define WW    64
#define QHH   128
#define QWW   128
#define HID   256
#define OUT3  1728      // C*9*3
#define NK    576       // C*9
#define EPSV  1e-6f

// pw table, transposed: row k (576) x 12 floats [s0o0 s0o1 s0o2 s1o0 ... s3o2]
__device__ float g_pwT[NK * 12];

// ---------------------------------------------------------------------------
// Kernel A: MLP for the 4 parity classes -> g_pwT. Atomic-free, init-free.
// grid = 108 blocks; each block owns 16 OUT3-columns, full j-reduction.
// ---------------------------------------------------------------------------
__global__ void __launch_bounds__(256) mlp_pw_kernel(
    const float* __restrict__ coord, const float* __restrict__ cell,
    const float* __restrict__ w1,    const float* __restrict__ b1,
    const float* __restrict__ w2,    const float* __restrict__ b2)
{
    __shared__ float s_h[4][HID];        // hdd for the 4 parity classes
    __shared__ float s_part[16][16][4];  // [jsub][col][s]

    int tid = threadIdx.x;

    {
        int j = tid;
        #pragma unroll
        for (int s = 0; s < 4; ++s) {
            int py = s >> 1, px = s & 1;
            int qs = py * QWW + px;           // representative query (batch 0)
            float cy = coord[qs * 2 + 0];
            float cx = coord[qs * 2 + 1];
            float ly = cell[qs * 2 + 0];
            float lx = cell[qs * 2 + 1];
            float cy_ = cy - ly * 0.5f;
            float cx_ = cx - lx * 0.5f;
            float cqy = fminf(fmaxf(cy_ + EPSV, -1.0f + EPSV), 1.0f - EPSV);
            float cqx = fminf(fmaxf(cx_ + EPSV, -1.0f + EPSV), 1.0f - EPSV);
            float fy = ((cqy + 1.0f) * 64.0f - 1.0f) * 0.5f;
            float fx = ((cqx + 1.0f) * 64.0f - 1.0f) * 0.5f;
            float iy = fminf(fmaxf(rintf(fy), 0.0f), 63.0f);
            float ix = fminf(fmaxf(rintf(fx), 0.0f), 63.0f);
            float qcy = -1.0f + 2.0f * iy / 64.0f;
            float qcx = -1.0f + 2.0f * ix / 64.0f;
            float ry = (cy_ - qcy) * 32.0f;
            float rx = (cx_ - qcx) * 32.0f;
            float rr = ly * 32.0f;
            float h = ry * w1[j] + rx * w1[HID + j] + rr * w1[2 * HID + j] + b1[j];
            s_h[s][j] = fmaxf(h, 0.0f);
        }
    }
    __syncthreads();

    int col  = tid & 15;                        // 0..15
    int jsub = tid >> 4;                        // 0..15
    int k3   = blockIdx.x * 16 + col;           // 0..1727
    int j0   = jsub * 16;

    float a0 = 0.f, a1 = 0.f, a2 = 0.f, a3 = 0.f;
    const float* wp = w2 + (size_t)j0 * OUT3 + k3;
    #pragma unroll
    for (int j = 0; j < 16; ++j) {
        float w = wp[(size_t)j * OUT3];
        int jj = j0 + j;
        a0 = fmaf(s_h[0][jj], w, a0);
        a1 = fmaf(s_h[1][jj], w, a1);
        a2 = fmaf(s_h[2][jj], w, a2);
        a3 = fmaf(s_h[3][jj], w, a3);
    }
    s_part[jsub][col][0] = a0;
    s_part[jsub][col][1] = a1;
    s_part[jsub][col][2] = a2;
    s_part[jsub][col][3] = a3;
    __syncthreads();

    if (tid < 64) {
        int oc = tid >> 2;          // 0..15
        int os = tid & 3;           // 0..3
        int k3o = blockIdx.x * 16 + oc;
        float v = b2[k3o];
        #pragma unroll
        for (int t = 0; t < 16; ++t) v += s_part[t][oc][os];
        int k = k3o / 3;
        int o = k3o - k * 3;
        g_pwT[k * 12 + os * 3 + o] = v;
    }
}

// ---------------------------------------------------------------------------
// f32x2 packed helpers (FFMA2 — PTX-only on sm_10x)
// ---------------------------------------------------------------------------
__device__ __forceinline__ void ffma2(unsigned long long& d,
                                      unsigned long long a,
                                      unsigned long long b)
{
    asm("fma.rn.f32x2 %0, %1, %2, %0;" : "+l"(d) : "l"(a), "l"(b));
}
__device__ __forceinline__ void addf2(unsigned long long& d, unsigned long long a)
{
    asm("add.rn.f32x2 %0, %0, %1;" : "+l"(d) : "l"(a));
}
__device__ __forceinline__ unsigned long long pack2(float f)
{
    unsigned long long r;
    asm("mov.b64 %0, {%1, %1};" : "=l"(r) : "f"(f));
    return r;
}

// ---------------------------------------------------------------------------
// Kernel B: half-row blocks for occupancy. 512 blocks x 256 threads.
// Block = 32 LR pixels (half a row). k (576 = 64ch x 9taps) split across the
// 8 warps (8 channels each). Lane owns 1 pixel x 12 outputs = 6 f32x2 accs.
// Per tap per lane: 1 LDS.32 + pack + 3 warp-uniform LDS.128 + 6 FFMA2.
// smem = 53.8KB -> 4 blocks/SM -> 32 warps/SM.
// ---------------------------------------------------------------------------
#define TW3  34
#define CHS  (3 * TW3)                  // 102 floats per channel (3 halo rows)
#define TILE_WORDS (CH * CHS)           // 6528
#define PW_WORDS   (NK * 12)            // 6912
#define SMEM_B ((TILE_WORDS + PW_WORDS) * 4)   // 53760 bytes

__global__ void __launch_bounds__(256) metasr_main_kernel(
    const float* __restrict__ feat, float* __restrict__ out)
{
    extern __shared__ float smem[];
    float* s_tile = smem;                  // [64][3][34]
    float* s_pw   = smem + TILE_WORDS;     // [576][12]

    int tid = threadIdx.x;
    int bx  = blockIdx.x;                  // 0..511
    int b   = bx >> 7;
    int rem = bx & 127;
    int y   = rem >> 1;                    // LR row 0..63
    int x0  = (rem & 1) * 32;              // half-row start

    // ---- pw table -> smem (float4) ----
    {
        const float4* src = (const float4*)g_pwT;
        float4* dst = (float4*)s_pw;
        for (int i = tid; i < PW_WORDS / 4; i += 256) dst[i] = src[i];
    }

    const float* fb = feat + (size_t)b * CH * HH * WW;

    // ---- halo columns: tile col 0 (gx = x0-1) and col 33 (gx = x0+32) ----
    for (int i = tid; i < CH * 3 * 2; i += 256) {
        int c    = i / 6;
        int rr   = (i % 6) >> 1;
        int side = i & 1;
        int gy   = y - 1 + rr;
        int gx   = x0 - 1 + side * 33;
        float v = 0.0f;
        if ((unsigned)gy < 64u && (unsigned)gx < 64u)
            v = fb[((c << 6) + gy) * 64 + gx];
        s_tile[c * CHS + rr * TW3 + side * 33] = v;
    }

    // ---- interior: 32 cols per row via float4 loads (scalar STS) ----
    for (int i = tid; i < CH * 3 * 8; i += 256) {     // 1536, 6 iters
        int c   = i / 24;
        int rem2 = i % 24;
        int rr  = rem2 >> 3;
        int q   = rem2 & 7;
        int gy  = y - 1 + rr;
        float4 v = make_float4(0.f, 0.f, 0.f, 0.f);
        if ((unsigned)gy < 64u)
            v = *(const float4*)(fb + ((c << 6) + gy) * 64 + x0 + q * 4);
        float* dst = s_tile + c * CHS + rr * TW3 + 1 + q * 4;
        dst[0] = v.x; dst[1] = v.y; dst[2] = v.z; dst[3] = v.w;
    }
    __syncthreads();

    // ---- main loop ----
    int w    = tid >> 5;
    int lane = tid & 31;

    const float* tc0 = s_tile + (w << 3) * CHS;          // warp's 8 channels
    const ulonglong2* pk0 = (const ulonglong2*)s_pw + (w * 72) * 3;

    unsigned long long acc[6];
    #pragma unroll
    for (int i = 0; i < 6; ++i) acc[i] = 0ull;

    #pragma unroll
    for (int cc = 0; cc < 8; ++cc) {
        const float* tc = tc0 + cc * CHS;
        const ulonglong2* pc = pk0 + cc * 27;   // 9 taps * 3 ull2
        #pragma unroll
        for (int t = 0; t < 9; ++t) {
            const int off = (t / 3) * TW3 + (t % 3);
            unsigned long long F = pack2(tc[off + lane]);
            ulonglong2 p01 = pc[t * 3 + 0];
            ulonglong2 p23 = pc[t * 3 + 1];
            ulonglong2 p45 = pc[t * 3 + 2];
            ffma2(acc[0], F, p01.x); ffma2(acc[1], F, p01.y);
            ffma2(acc[2], F, p23.x); ffma2(acc[3], F, p23.y);
            ffma2(acc[4], F, p45.x); ffma2(acc[5], F, p45.y);
        }
    }

    // ---- cross-warp reduction: s_red[w][a(6)][33] padded, conflict-light ----
    __syncthreads();
    unsigned long long* s_red = (unsigned long long*)smem;
    #pragma unroll
    for (int a = 0; a < 6; ++a)
        s_red[(w * 6 + a) * 33 + lane] = acc[a];
    __syncthreads();

    // pass 2: 192 output ull (32 pixels x 6); thread -> (pixel p, a)
    if (tid < 192) {
        int p  = tid / 6;
        int a  = tid % 6;
        int py = a / 3;              // which HR row of the 2x2
        int jj = a % 3;              // which ull within that row's 6 floats

        unsigned long long v = s_red[a * 33 + p];
        #pragma unroll
        for (int ww = 1; ww < 8; ++ww)
            addf2(v, s_red[(ww * 6 + a) * 33 + p]);

        int yq = 2 * y + py;
        int xq = 2 * (x0 + p);
        size_t base = ((size_t)(b * QHH + yq) * QWW + xq) * 3 + jj * 2;
        *(unsigned long long*)(out + base) = v;
    }
}

// ---------------------------------------------------------------------------
extern "C" void kernel_launch(void* const* d_in, const int* in_sizes, int n_in,
                              void* d_out, int out_size)
{
    const float* feat  = (const float*)d_in[0];
    const float* coord = (const float*)d_in[1];
    const float* cell  = (const float*)d_in[2];
    const float* w1    = (const float*)d_in[3];
    const float* b1    = (const float*)d_in[4];
    const float* w2    = (const float*)d_in[5];
    const float* b2    = (const float*)d_in[6];
    float* out = (float*)d_out;

    cudaFuncSetAttribute(metasr_main_kernel,
                         cudaFuncAttributeMaxDynamicSharedMemorySize, SMEM_B);

    mlp_pw_kernel<<<108, 256>>>(coord, cell, w1, b1, w2, b2);
    metasr_main_kernel<<<512, 256, SMEM_B>>>(feat, out);
}

// round 7
// speedup vs baseline: 1.2471x; 1.2471x over previous
#include <cuda_runtime.h>
#include <cstdint>

// Problem constants
#define BATCH 4
#define CH    64
#define HH    64
#define WW    64
#define QHH   128
#define QWW   128
#define HID   256
#define OUT3  1728      // C*9*3
#define NK    576       // C*9
#define EPSV  1e-6f

// pw table, transposed: row k (576) x 12 floats [s0o0 s0o1 s0o2 s1o0 ... s3o2]
__device__ float g_pwT[NK * 12];

// ---------------------------------------------------------------------------
// Kernel A: MLP for the 4 parity classes -> g_pwT. Atomic-free, init-free.
// ---------------------------------------------------------------------------
__global__ void __launch_bounds__(256) mlp_pw_kernel(
    const float* __restrict__ coord, const float* __restrict__ cell,
    const float* __restrict__ w1,    const float* __restrict__ b1,
    const float* __restrict__ w2,    const float* __restrict__ b2)
{
    __shared__ float s_h[4][HID];        // hdd for the 4 parity classes
    __shared__ float s_part[16][16][4];  // [jsub][col][s]

    int tid = threadIdx.x;

    {
        int j = tid;
        #pragma unroll
        for (int s = 0; s < 4; ++s) {
            int py = s >> 1, px = s & 1;
            int qs = py * QWW + px;           // representative query (batch 0)
            float cy = coord[qs * 2 + 0];
            float cx = coord[qs * 2 + 1];
            float ly = cell[qs * 2 + 0];
            float lx = cell[qs * 2 + 1];
            float cy_ = cy - ly * 0.5f;
            float cx_ = cx - lx * 0.5f;
            float cqy = fminf(fmaxf(cy_ + EPSV, -1.0f + EPSV), 1.0f - EPSV);
            float cqx = fminf(fmaxf(cx_ + EPSV, -1.0f + EPSV), 1.0f - EPSV);
            float fy = ((cqy + 1.0f) * 64.0f - 1.0f) * 0.5f;
            float fx = ((cqx + 1.0f) * 64.0f - 1.0f) * 0.5f;
            float iy = fminf(fmaxf(rintf(fy), 0.0f), 63.0f);
            float ix = fminf(fmaxf(rintf(fx), 0.0f), 63.0f);
            float qcy = -1.0f + 2.0f * iy / 64.0f;
            float qcx = -1.0f + 2.0f * ix / 64.0f;
            float ry = (cy_ - qcy) * 32.0f;
            float rx = (cx_ - qcx) * 32.0f;
            float rr = ly * 32.0f;
            float h = ry * w1[j] + rx * w1[HID + j] + rr * w1[2 * HID + j] + b1[j];
            s_h[s][j] = fmaxf(h, 0.0f);
        }
    }
    __syncthreads();

    int col  = tid & 15;                        // 0..15
    int jsub = tid >> 4;                        // 0..15
    int k3   = blockIdx.x * 16 + col;           // 0..1727
    int j0   = jsub * 16;

    float a0 = 0.f, a1 = 0.f, a2 = 0.f, a3 = 0.f;
    const float* wp = w2 + (size_t)j0 * OUT3 + k3;
    #pragma unroll
    for (int j = 0; j < 16; ++j) {
        float w = wp[(size_t)j * OUT3];
        int jj = j0 + j;
        a0 = fmaf(s_h[0][jj], w, a0);
        a1 = fmaf(s_h[1][jj], w, a1);
        a2 = fmaf(s_h[2][jj], w, a2);
        a3 = fmaf(s_h[3][jj], w, a3);
    }
    s_part[jsub][col][0] = a0;
    s_part[jsub][col][1] = a1;
    s_part[jsub][col][2] = a2;
    s_part[jsub][col][3] = a3;
    __syncthreads();

    if (tid < 64) {
        int oc = tid >> 2;          // 0..15
        int os = tid & 3;           // 0..3
        int k3o = blockIdx.x * 16 + oc;
        float v = b2[k3o];
        #pragma unroll
        for (int t = 0; t < 16; ++t) v += s_part[t][oc][os];
        int k = k3o / 3;
        int o = k3o - k * 3;
        g_pwT[k * 12 + os * 3 + o] = v;
    }
}

// ---------------------------------------------------------------------------
// f32x2 packed helpers (FFMA2 — PTX-only on sm_10x)
// ---------------------------------------------------------------------------
__device__ __forceinline__ void ffma2(unsigned long long& d,
                                      unsigned long long a,
                                      unsigned long long b)
{
    asm("fma.rn.f32x2 %0, %1, %2, %0;" : "+l"(d) : "l"(a), "l"(b));
}
__device__ __forceinline__ void addf2(unsigned long long& d, unsigned long long a)
{
    asm("add.rn.f32x2 %0, %0, %1;" : "+l"(d) : "l"(a));
}
__device__ __forceinline__ unsigned long long pack2(float f)
{
    unsigned long long r;
    asm("mov.b64 %0, {%1, %1};" : "=l"(r) : "f"(f));
    return r;
}

// ---------------------------------------------------------------------------
// Kernel B: 2 pixels per lane. 256 blocks x 256 threads (8 warps).
// Block = 2 LR rows x 32 cols (64 pixels). k (576 = 64ch x 9taps) split
// across 8 warps (8 ch each); warp covers all 64 pixels, lane owns the
// (row0,col=lane) and (row1,col=lane) pixels -> 12 f32x2 accumulators.
// Per channel per lane: 12 feat LDS.32 (row-reuse across the 2 pixels) +
// 12 packs + 27 warp-uniform pw LDS.128 + 108 FFMA2  ->  FMA-pipe bound.
// smem = 62.4KB -> 3 blocks/SM -> 24 warps/SM.
// ---------------------------------------------------------------------------
#define TW3   34
#define NROWS 4
#define CHS   (NROWS * TW3)             // 136 floats per channel
#define TILE_WORDS (CH * CHS)           // 8704
#define PW_WORDS   (NK * 12)            // 6912
#define SMEM_B ((TILE_WORDS + PW_WORDS) * 4)   // 62464 bytes

__global__ void __launch_bounds__(256, 3) metasr_main_kernel(
    const float* __restrict__ feat, float* __restrict__ out)
{
    extern __shared__ float smem[];
    float* s_tile = smem;                  // [64][4][34]
    float* s_pw   = smem + TILE_WORDS;     // [576][12]

    int tid = threadIdx.x;
    int bx  = blockIdx.x;                  // 0..255
    int b   = bx >> 6;
    int y0  = ((bx >> 1) & 31) * 2;        // first of 2 LR rows
    int x0  = (bx & 1) * 32;               // column half

    // ---- pw table -> smem (float4) ----
    {
        const float4* src = (const float4*)g_pwT;
        float4* dst = (float4*)s_pw;
        for (int i = tid; i < PW_WORDS / 4; i += 256) dst[i] = src[i];
    }

    const float* fb = feat + (size_t)b * CH * HH * WW;

    // ---- halo columns: tile col 0 (gx = x0-1) and col 33 (gx = x0+32) ----
    for (int i = tid; i < CH * NROWS * 2; i += 256) {   // 512 -> 2 iters
        int c    = i >> 3;
        int rr   = (i >> 1) & 3;
        int side = i & 1;
        int gy   = y0 - 1 + rr;
        int gx   = x0 - 1 + side * 33;
        float v = 0.0f;
        if ((unsigned)gy < 64u && (unsigned)gx < 64u)
            v = fb[((c << 6) + gy) * 64 + gx];
        s_tile[c * CHS + rr * TW3 + side * 33] = v;
    }

    // ---- interior: 32 cols per row via float4 loads ----
    for (int i = tid; i < CH * NROWS * 8; i += 256) {   // 2048 -> 8 iters
        int c   = i >> 5;
        int rr  = (i >> 3) & 3;
        int q   = i & 7;
        int gy  = y0 - 1 + rr;
        float4 v = make_float4(0.f, 0.f, 0.f, 0.f);
        if ((unsigned)gy < 64u)
            v = *(const float4*)(fb + ((c << 6) + gy) * 64 + x0 + q * 4);
        float* dst = s_tile + c * CHS + rr * TW3 + 1 + q * 4;
        dst[0] = v.x; dst[1] = v.y; dst[2] = v.z; dst[3] = v.w;
    }
    __syncthreads();

    // ---- main loop ----
    int w    = tid >> 5;
    int lane = tid & 31;

    const float* tw8 = s_tile + (w << 3) * CHS + lane;   // warp's 8 channels
    const ulonglong2* pk0 = (const ulonglong2*)s_pw + (w * 72) * 3;

    unsigned long long acc[12];
    #pragma unroll
    for (int i = 0; i < 12; ++i) acc[i] = 0ull;

    #pragma unroll
    for (int cc = 0; cc < 8; ++cc) {
        const float* tc = tw8 + cc * CHS;
        const ulonglong2* pc = pk0 + cc * 27;   // 9 taps * 3 ull2

        // 12 row/dx feat values, packed once (rows shared by the 2 pixels)
        unsigned long long R[4][3];
        #pragma unroll
        for (int rr = 0; rr < 4; ++rr)
            #pragma unroll
            for (int dx = 0; dx < 3; ++dx)
                R[rr][dx] = pack2(tc[rr * TW3 + dx]);

        #pragma unroll
        for (int dy = 0; dy < 3; ++dy) {
            #pragma unroll
            for (int dx = 0; dx < 3; ++dx) {
                const ulonglong2* p = pc + (dy * 3 + dx) * 3;
                ulonglong2 p01 = p[0];
                ulonglong2 p23 = p[1];
                ulonglong2 p45 = p[2];
                unsigned long long F0 = R[dy][dx];
                unsigned long long F1 = R[dy + 1][dx];
                ffma2(acc[0],  F0, p01.x); ffma2(acc[1],  F0, p01.y);
                ffma2(acc[2],  F0, p23.x); ffma2(acc[3],  F0, p23.y);
                ffma2(acc[4],  F0, p45.x); ffma2(acc[5],  F0, p45.y);
                ffma2(acc[6],  F1, p01.x); ffma2(acc[7],  F1, p01.y);
                ffma2(acc[8],  F1, p23.x); ffma2(acc[9],  F1, p23.y);
                ffma2(acc[10], F1, p45.x); ffma2(acc[11], F1, p45.y);
            }
        }
    }

    // ---- cross-warp reduction: s_red[w][a(12)][33] padded ----
    __syncthreads();
    unsigned long long* s_red = (unsigned long long*)smem;
    #pragma unroll
    for (int a = 0; a < 12; ++a)
        s_red[(w * 12 + a) * 33 + lane] = acc[a];
    __syncthreads();

    // pass 2: 384 output ull = (r 2) x (col 32) x (a 6)
    for (int i = tid; i < 384; i += 256) {
        int r   = i / 192;
        int rem = i - r * 192;
        int col = rem / 6;
        int a   = rem - col * 6;

        int srcidx = r * 6 + a;
        unsigned long long v = s_red[srcidx * 33 + col];
        #pragma unroll
        for (int ww = 1; ww < 8; ++ww)
            addf2(v, s_red[(ww * 12 + srcidx) * 33 + col]);

        int yq = 2 * (y0 + r) + (a / 3);     // a: 0-2 -> HR row 2y, 3-5 -> 2y+1
        int xq = 2 * (x0 + col);
        int jj = a % 3;
        size_t base = ((size_t)(b * QHH + yq) * QWW + xq) * 3 + jj * 2;
        *(unsigned long long*)(out + base) = v;
    }
}

// ---------------------------------------------------------------------------
extern "C" void kernel_launch(void* const* d_in, const int* in_sizes, int n_in,
                              void* d_out, int out_size)
{
    const float* feat  = (const float*)d_in[0];
    const float* coord = (const float*)d_in[1];
    const float* cell  = (const float*)d_in[2];
    const float* w1    = (const float*)d_in[3];
    const float* b1    = (const float*)d_in[4];
    const float* w2    = (const float*)d_in[5];
    const float* b2    = (const float*)d_in[6];
    float* out = (float*)d_out;

    cudaFuncSetAttribute(metasr_main_kernel,
                         cudaFuncAttributeMaxDynamicSharedMemorySize, SMEM_B);

    mlp_pw_kernel<<<108, 256>>>(coord, cell, w1, b1, w2, b2);
    metasr_main_kernel<<<256, 256, SMEM_B>>>(feat, out);
}

// round 8
// speedup vs baseline: 1.3253x; 1.0626x over previous
#include <cuda_runtime.h>
#include <cstdint>

// Problem constants
#define BATCH 4
#define CH    64
#define HH    64
#define WW    64
#define QHH   128
#define QWW   128
#define HID   256
#define OUT3  1728      // C*9*3
#define NK    576       // C*9
#define EPSV  1e-6f

// pw table, transposed: row k (576) x 12 floats [s0o0 s0o1 s0o2 s1o0 ... s3o2]
__device__ float g_pwT[NK * 12];

// ---------------------------------------------------------------------------
// Kernel A: MLP for the 4 parity classes -> g_pwT. Atomic-free, init-free.
// ---------------------------------------------------------------------------
__global__ void __launch_bounds__(256) mlp_pw_kernel(
    const float* __restrict__ coord, const float* __restrict__ cell,
    const float* __restrict__ w1,    const float* __restrict__ b1,
    const float* __restrict__ w2,    const float* __restrict__ b2)
{
    __shared__ float s_h[4][HID];        // hdd for the 4 parity classes
    __shared__ float s_part[16][16][4];  // [jsub][col][s]

    int tid = threadIdx.x;

    {
        int j = tid;
        #pragma unroll
        for (int s = 0; s < 4; ++s) {
            int py = s >> 1, px = s & 1;
            int qs = py * QWW + px;           // representative query (batch 0)
            float cy = coord[qs * 2 + 0];
            float cx = coord[qs * 2 + 1];
            float ly = cell[qs * 2 + 0];
            float lx = cell[qs * 2 + 1];
            float cy_ = cy - ly * 0.5f;
            float cx_ = cx - lx * 0.5f;
            float cqy = fminf(fmaxf(cy_ + EPSV, -1.0f + EPSV), 1.0f - EPSV);
            float cqx = fminf(fmaxf(cx_ + EPSV, -1.0f + EPSV), 1.0f - EPSV);
            float fy = ((cqy + 1.0f) * 64.0f - 1.0f) * 0.5f;
            float fx = ((cqx + 1.0f) * 64.0f - 1.0f) * 0.5f;
            float iy = fminf(fmaxf(rintf(fy), 0.0f), 63.0f);
            float ix = fminf(fmaxf(rintf(fx), 0.0f), 63.0f);
            float qcy = -1.0f + 2.0f * iy / 64.0f;
            float qcx = -1.0f + 2.0f * ix / 64.0f;
            float ry = (cy_ - qcy) * 32.0f;
            float rx = (cx_ - qcx) * 32.0f;
            float rr = ly * 32.0f;
            float h = ry * w1[j] + rx * w1[HID + j] + rr * w1[2 * HID + j] + b1[j];
            s_h[s][j] = fmaxf(h, 0.0f);
        }
    }
    __syncthreads();

    int col  = tid & 15;                        // 0..15
    int jsub = tid >> 4;                        // 0..15
    int k3   = blockIdx.x * 16 + col;           // 0..1727
    int j0   = jsub * 16;

    float a0 = 0.f, a1 = 0.f, a2 = 0.f, a3 = 0.f;
    const float* wp = w2 + (size_t)j0 * OUT3 + k3;
    #pragma unroll
    for (int j = 0; j < 16; ++j) {
        float w = wp[(size_t)j * OUT3];
        int jj = j0 + j;
        a0 = fmaf(s_h[0][jj], w, a0);
        a1 = fmaf(s_h[1][jj], w, a1);
        a2 = fmaf(s_h[2][jj], w, a2);
        a3 = fmaf(s_h[3][jj], w, a3);
    }
    s_part[jsub][col][0] = a0;
    s_part[jsub][col][1] = a1;
    s_part[jsub][col][2] = a2;
    s_part[jsub][col][3] = a3;
    __syncthreads();

    if (tid < 64) {
        int oc = tid >> 2;          // 0..15
        int os = tid & 3;           // 0..3
        int k3o = blockIdx.x * 16 + oc;
        float v = b2[k3o];
        #pragma unroll
        for (int t = 0; t < 16; ++t) v += s_part[t][oc][os];
        int k = k3o / 3;
        int o = k3o - k * 3;
        g_pwT[k * 12 + os * 3 + o] = v;
    }
}

// ---------------------------------------------------------------------------
// f32x2 packed helpers (FFMA2 — PTX-only on sm_10x)
// ---------------------------------------------------------------------------
__device__ __forceinline__ void ffma2(unsigned long long& d,
                                      unsigned long long a,
                                      unsigned long long b)
{
    asm("fma.rn.f32x2 %0, %1, %2, %0;" : "+l"(d) : "l"(a), "l"(b));
}
__device__ __forceinline__ void addf2(unsigned long long& d, unsigned long long a)
{
    asm("add.rn.f32x2 %0, %0, %1;" : "+l"(d) : "l"(a));
}
__device__ __forceinline__ unsigned long long pack2(float f)
{
    unsigned long long r;
    asm("mov.b64 %0, {%1, %1};" : "=l"(r) : "f"(f));
    return r;
}

// ---------------------------------------------------------------------------
// Kernel B: 512-thread blocks (16 warps) so each SM holds 32 resident warps.
// Block = 2 LR rows x 32 cols (64 pixels), grid 256 (2 blocks/SM on 108 SMs).
// k (576 = 64ch x 9taps) split across 16 warps -> 4 channels per warp.
// Lane owns the (row0,col) & (row1,col) pixels -> 12 f32x2 accumulators.
// Per channel per lane: 12 feat LDS.32 (row-reuse) + 12 packs +
// 27 warp-uniform pw LDS.128 + 108 FFMA2.
// smem = 62.4KB, launch_bounds(512,2) -> regs<=64 -> 2 blocks/SM.
// ---------------------------------------------------------------------------
#define TW3   34
#define NROWS 4
#define CHS   (NROWS * TW3)             // 136 floats per channel
#define TILE_WORDS (CH * CHS)           // 8704
#define PW_WORDS   (NK * 12)            // 6912
#define SMEM_B ((TILE_WORDS + PW_WORDS) * 4)   // 62464 bytes

__global__ void __launch_bounds__(512, 2) metasr_main_kernel(
    const float* __restrict__ feat, float* __restrict__ out)
{
    extern __shared__ float smem[];
    float* s_tile = smem;                  // [64][4][34]
    float* s_pw   = smem + TILE_WORDS;     // [576][12]

    int tid = threadIdx.x;
    int bx  = blockIdx.x;                  // 0..255
    int b   = bx >> 6;
    int y0  = ((bx >> 1) & 31) * 2;        // first of 2 LR rows
    int x0  = (bx & 1) * 32;               // column half

    // ---- pw table -> smem (float4) ----
    {
        const float4* src = (const float4*)g_pwT;
        float4* dst = (float4*)s_pw;
        for (int i = tid; i < PW_WORDS / 4; i += 512) dst[i] = src[i];
    }

    const float* fb = feat + (size_t)b * CH * HH * WW;

    // ---- halo columns: tile col 0 (gx = x0-1) and col 33 (gx = x0+32) ----
    {
        int i = tid;                                   // 512 -> exactly 1 iter
        int c    = i >> 3;
        int rr   = (i >> 1) & 3;
        int side = i & 1;
        int gy   = y0 - 1 + rr;
        int gx   = x0 - 1 + side * 33;
        float v = 0.0f;
        if ((unsigned)gy < 64u && (unsigned)gx < 64u)
            v = fb[((c << 6) + gy) * 64 + gx];
        s_tile[c * CHS + rr * TW3 + side * 33] = v;
    }

    // ---- interior: 32 cols per row via float4 loads ----
    #pragma unroll
    for (int it = 0; it < 4; ++it) {                   // 2048 total
        int i   = it * 512 + tid;
        int c   = i >> 5;
        int rr  = (i >> 3) & 3;
        int q   = i & 7;
        int gy  = y0 - 1 + rr;
        float4 v = make_float4(0.f, 0.f, 0.f, 0.f);
        if ((unsigned)gy < 64u)
            v = *(const float4*)(fb + ((c << 6) + gy) * 64 + x0 + q * 4);
        float* dst = s_tile + c * CHS + rr * TW3 + 1 + q * 4;
        dst[0] = v.x; dst[1] = v.y; dst[2] = v.z; dst[3] = v.w;
    }
    __syncthreads();

    // ---- main loop: warp w owns channels [4w, 4w+4) ----
    int w    = tid >> 5;
    int lane = tid & 31;

    const float* tw4 = s_tile + (w << 2) * CHS + lane;
    const ulonglong2* pk0 = (const ulonglong2*)s_pw + (w * 36) * 3;  // 36 k-rows

    unsigned long long acc[12];
    #pragma unroll
    for (int i = 0; i < 12; ++i) acc[i] = 0ull;

    #pragma unroll
    for (int cc = 0; cc < 4; ++cc) {
        const float* tc = tw4 + cc * CHS;
        const ulonglong2* pc = pk0 + cc * 27;   // 9 taps * 3 ull2

        // 12 row/dx feat values, packed once (rows shared by the 2 pixels)
        unsigned long long R[4][3];
        #pragma unroll
        for (int rr = 0; rr < 4; ++rr)
            #pragma unroll
            for (int dx = 0; dx < 3; ++dx)
                R[rr][dx] = pack2(tc[rr * TW3 + dx]);

        #pragma unroll
        for (int dy = 0; dy < 3; ++dy) {
            #pragma unroll
            for (int dx = 0; dx < 3; ++dx) {
                const ulonglong2* p = pc + (dy * 3 + dx) * 3;
                ulonglong2 p01 = p[0];
                ulonglong2 p23 = p[1];
                ulonglong2 p45 = p[2];
                unsigned long long F0 = R[dy][dx];
                unsigned long long F1 = R[dy + 1][dx];
                ffma2(acc[0],  F0, p01.x); ffma2(acc[1],  F0, p01.y);
                ffma2(acc[2],  F0, p23.x); ffma2(acc[3],  F0, p23.y);
                ffma2(acc[4],  F0, p45.x); ffma2(acc[5],  F0, p45.y);
                ffma2(acc[6],  F1, p01.x); ffma2(acc[7],  F1, p01.y);
                ffma2(acc[8],  F1, p23.x); ffma2(acc[9],  F1, p23.y);
                ffma2(acc[10], F1, p45.x); ffma2(acc[11], F1, p45.y);
            }
        }
    }

    // ---- cross-warp reduction: s_red[w(16)][a(12)][33] padded ull ----
    __syncthreads();
    unsigned long long* s_red = (unsigned long long*)smem;
    #pragma unroll
    for (int a = 0; a < 12; ++a)
        s_red[(w * 12 + a) * 33 + lane] = acc[a];
    __syncthreads();

    // pass 2: 384 output ull = (r 2) x (col 32) x (a 6); 16-way reduce
    if (tid < 384) {
        int r   = tid / 192;
        int rem = tid - r * 192;
        int col = rem / 6;
        int a   = rem - col * 6;

        int srcidx = r * 6 + a;
        unsigned long long v = s_red[srcidx * 33 + col];
        #pragma unroll
        for (int ww = 1; ww < 16; ++ww)
            addf2(v, s_red[(ww * 12 + srcidx) * 33 + col]);

        int yq = 2 * (y0 + r) + (a / 3);     // a: 0-2 -> HR row 2y, 3-5 -> 2y+1
        int xq = 2 * (x0 + col);
        int jj = a % 3;
        size_t base = ((size_t)(b * QHH + yq) * QWW + xq) * 3 + jj * 2;
        *(unsigned long long*)(out + base) = v;
    }
}

// ---------------------------------------------------------------------------
extern "C" void kernel_launch(void* const* d_in, const int* in_sizes, int n_in,
                              void* d_out, int out_size)
{
    const float* feat  = (const float*)d_in[0];
    const float* coord = (const float*)d_in[1];
    const float* cell  = (const float*)d_in[2];
    const float* w1    = (const float*)d_in[3];
    const float* b1    = (const float*)d_in[4];
    const float* w2    = (const float*)d_in[5];
    const float* b2    = (const float*)d_in[6];
    float* out = (float*)d_out;

    cudaFuncSetAttribute(metasr_main_kernel,
                         cudaFuncAttributeMaxDynamicSharedMemorySize, SMEM_B);

    mlp_pw_kernel<<<108, 256>>>(coord, cell, w1, b1, w2, b2);
    metasr_main_kernel<<<256, 512, SMEM_B>>>(feat, out);
}

// round 11
// speedup vs baseline: 1.4168x; 1.0691x over previous
#include <cuda_runtime.h>
#include <cstdint>

// Problem constants
#define BATCH 4
#define CH    64
#define HH    64
#define WW    64
#define QHH   128
#define QWW   128
#define HID   256
#define OUT3  1728      // C*9*3
#define NK    576       // C*9
#define EPSV  1e-6f

// pw table, transposed: row k (576) x 12 floats [s0o0 s0o1 s0o2 s1o0 ... s3o2]
__device__ float g_pwT[NK * 12];

// ---------------------------------------------------------------------------
// Kernel A: MLP for the 4 parity classes -> g_pwT. Atomic-free, init-free.
// ---------------------------------------------------------------------------
__global__ void __launch_bounds__(256) mlp_pw_kernel(
    const float* __restrict__ coord, const float* __restrict__ cell,
    const float* __restrict__ w1,    const float* __restrict__ b1,
    const float* __restrict__ w2,    const float* __restrict__ b2)
{
    __shared__ float s_h[4][HID];        // hdd for the 4 parity classes
    __shared__ float s_part[16][16][4];  // [jsub][col][s]

    int tid = threadIdx.x;

    {
        int j = tid;
        #pragma unroll
        for (int s = 0; s < 4; ++s) {
            int py = s >> 1, px = s & 1;
            int qs = py * QWW + px;           // representative query (batch 0)
            float cy = coord[qs * 2 + 0];
            float cx = coord[qs * 2 + 1];
            float ly = cell[qs * 2 + 0];
            float lx = cell[qs * 2 + 1];
            float cy_ = cy - ly * 0.5f;
            float cx_ = cx - lx * 0.5f;
            float cqy = fminf(fmaxf(cy_ + EPSV, -1.0f + EPSV), 1.0f - EPSV);
            float cqx = fminf(fmaxf(cx_ + EPSV, -1.0f + EPSV), 1.0f - EPSV);
            float fy = ((cqy + 1.0f) * 64.0f - 1.0f) * 0.5f;
            float fx = ((cqx + 1.0f) * 64.0f - 1.0f) * 0.5f;
            float iy = fminf(fmaxf(rintf(fy), 0.0f), 63.0f);
            float ix = fminf(fmaxf(rintf(fx), 0.0f), 63.0f);
            float qcy = -1.0f + 2.0f * iy / 64.0f;
            float qcx = -1.0f + 2.0f * ix / 64.0f;
            float ry = (cy_ - qcy) * 32.0f;
            float rx = (cx_ - qcx) * 32.0f;
            float rr = ly * 32.0f;
            float h = ry * w1[j] + rx * w1[HID + j] + rr * w1[2 * HID + j] + b1[j];
            s_h[s][j] = fmaxf(h, 0.0f);
        }
    }
    __syncthreads();

    int col  = tid & 15;                        // 0..15
    int jsub = tid >> 4;                        // 0..15
    int k3   = blockIdx.x * 16 + col;           // 0..1727
    int j0   = jsub * 16;

    float a0 = 0.f, a1 = 0.f, a2 = 0.f, a3 = 0.f;
    const float* wp = w2 + (size_t)j0 * OUT3 + k3;
    #pragma unroll
    for (int j = 0; j < 16; ++j) {
        float w = wp[(size_t)j * OUT3];
        int jj = j0 + j;
        a0 = fmaf(s_h[0][jj], w, a0);
        a1 = fmaf(s_h[1][jj], w, a1);
        a2 = fmaf(s_h[2][jj], w, a2);
        a3 = fmaf(s_h[3][jj], w, a3);
    }
    s_part[jsub][col][0] = a0;
    s_part[jsub][col][1] = a1;
    s_part[jsub][col][2] = a2;
    s_part[jsub][col][3] = a3;
    __syncthreads();

    if (tid < 64) {
        int oc = tid >> 2;          // 0..15
        int os = tid & 3;           // 0..3
        int k3o = blockIdx.x * 16 + oc;
        float v = b2[k3o];
        #pragma unroll
        for (int t = 0; t < 16; ++t) v += s_part[t][oc][os];
        int k = k3o / 3;
        int o = k3o - k * 3;
        g_pwT[k * 12 + os * 3 + o] = v;
    }
}

// ---------------------------------------------------------------------------
// f32x2 packed helpers (FFMA2 — PTX-only on sm_10x)
// ---------------------------------------------------------------------------
__device__ __forceinline__ void ffma2(unsigned long long& d,
                                      unsigned long long a,
                                      unsigned long long b)
{
    asm("fma.rn.f32x2 %0, %1, %2, %0;" : "+l"(d) : "l"(a), "l"(b));
}
__device__ __forceinline__ void addf2(unsigned long long& d, unsigned long long a)
{
    asm("add.rn.f32x2 %0, %0, %1;" : "+l"(d) : "l"(a));
}
__device__ __forceinline__ unsigned long long pack2(float f)
{
    unsigned long long r;
    asm("mov.b64 %0, {%1, %1};" : "=l"(r) : "f"(f));
    return r;
}

// ---------------------------------------------------------------------------
// Kernel B: 4 pixels per lane, 1 block/SM, NO register spills.
// grid = 128 (one uniform wave), block = 512 threads (16 warps).
// Block = 4 LR rows x 32 cols (128 px). k (576 = 64ch x 9taps) split across
// 16 warps -> 4 channels each. Lane owns pixels (row0..row3, col=lane)
// -> 24 f32x2 accumulators. Per channel per lane: 18 feat LDS.32 (6 rows x
// 3 dx, shared across the 4 pixel rows) + 18 packs + 27 uniform pw LDS.128
// + 216 FFMA2 (77% FFMA2 density). 1 block/SM -> 128 regs available.
// ---------------------------------------------------------------------------
#define TW3   34
#define NROWS 6
#define CHS   (NROWS * TW3)             // 204 floats per channel
#define TILE_WORDS (CH * CHS)           // 13056
#define PW_WORDS   (NK * 12)            // 6912
// reduction view: [16 warps][24 accs][33] ull = 101376 B (> tile+pw = 79872)
#define SMEM_B (16 * 24 * 33 * 8)

__global__ void __launch_bounds__(512, 1) metasr_main_kernel(
    const float* __restrict__ feat, float* __restrict__ out)
{
    extern __shared__ float smem[];
    float* s_tile = smem;                  // [64][6][34]
    float* s_pw   = smem + TILE_WORDS;     // [576][12]

    int tid = threadIdx.x;
    int bx  = blockIdx.x;                  // 0..127
    int b   = bx >> 5;
    int y0  = ((bx >> 1) & 15) * 4;        // first of 4 LR rows
    int x0  = (bx & 1) * 32;               // column half

    // ---- pw table -> smem (float4) ----
    {
        const float4* src = (const float4*)g_pwT;
        float4* dst = (float4*)s_pw;
        for (int i = tid; i < PW_WORDS / 4; i += 512) dst[i] = src[i];
    }

    const float* fb = feat + (size_t)b * CH * HH * WW;

    // ---- halo columns: tile col 0 (gx = x0-1) and col 33 (gx = x0+32) ----
    for (int i = tid; i < CH * NROWS * 2; i += 512) {   // 768
        int c    = i / 12;
        int rem  = i - c * 12;
        int rr   = rem >> 1;
        int side = rem & 1;
        int gy   = y0 - 1 + rr;
        int gx   = x0 - 1 + side * 33;
        float v = 0.0f;
        if ((unsigned)gy < 64u && (unsigned)gx < 64u)
            v = fb[((c << 6) + gy) * 64 + gx];
        s_tile[c * CHS + rr * TW3 + side * 33] = v;
    }

    // ---- interior: 32 cols per row via float4 loads ----
    #pragma unroll
    for (int it = 0; it < 6; ++it) {                    // 3072 total
        int i   = it * 512 + tid;
        int c   = i / 48;
        int rem = i - c * 48;
        int rr  = rem >> 3;
        int q   = rem & 7;
        int gy  = y0 - 1 + rr;
        float4 v = make_float4(0.f, 0.f, 0.f, 0.f);
        if ((unsigned)gy < 64u)
            v = *(const float4*)(fb + ((c << 6) + gy) * 64 + x0 + q * 4);
        float* dst = s_tile + c * CHS + rr * TW3 + 1 + q * 4;
        dst[0] = v.x; dst[1] = v.y; dst[2] = v.z; dst[3] = v.w;
    }
    __syncthreads();

    // ---- main loop: warp w owns channels [4w, 4w+4) ----
    int w    = tid >> 5;
    int lane = tid & 31;

    const float* tw4 = s_tile + (w << 2) * CHS + lane;
    const ulonglong2* pk0 = (const ulonglong2*)s_pw + (w * 36) * 3;  // 36 k-rows

    unsigned long long acc[24];
    #pragma unroll
    for (int i = 0; i < 24; ++i) acc[i] = 0ull;

    #pragma unroll
    for (int cc = 0; cc < 4; ++cc) {
        const float* tc = tw4 + cc * CHS;
        const ulonglong2* pc = pk0 + cc * 27;   // 9 taps * 3 ull2

        // 18 row/dx feat values, packed once (rows shared by the 4 pixels)
        unsigned long long R[6][3];
        #pragma unroll
        for (int rr = 0; rr < 6; ++rr)
            #pragma unroll
            for (int dx = 0; dx < 3; ++dx)
                R[rr][dx] = pack2(tc[rr * TW3 + dx]);

        #pragma unroll
        for (int dy = 0; dy < 3; ++dy) {
            #pragma unroll
            for (int dx = 0; dx < 3; ++dx) {
                const ulonglong2* p = pc + (dy * 3 + dx) * 3;
                ulonglong2 p01 = p[0];
                ulonglong2 p23 = p[1];
                ulonglong2 p45 = p[2];
                #pragma unroll
                for (int r = 0; r < 4; ++r) {
                    unsigned long long F = R[dy + r][dx];
                    ffma2(acc[r * 6 + 0], F, p01.x);
                    ffma2(acc[r * 6 + 1], F, p01.y);
                    ffma2(acc[r * 6 + 2], F, p23.x);
                    ffma2(acc[r * 6 + 3], F, p23.y);
                    ffma2(acc[r * 6 + 4], F, p45.x);
                    ffma2(acc[r * 6 + 5], F, p45.y);
                }
            }
        }
    }

    // ---- cross-warp reduction: s_red[w(16)][a(24)][33] padded ull ----
    __syncthreads();
    unsigned long long* s_red = (unsigned long long*)smem;
    #pragma unroll
    for (int a = 0; a < 24; ++a)
        s_red[(w * 24 + a) * 33 + lane] = acc[a];
    __syncthreads();

    // pass 2: 768 output ull = (r 4) x (col 32) x (a 6); 16-way reduce
    #pragma unroll
    for (int ii = 0; ii < 2; ++ii) {
        int i = ii * 512 + tid;
        if (i < 768) {
            int r   = i / 192;
            int rem = i - r * 192;
            int col = rem / 6;
            int a   = rem - col * 6;

            int srcidx = r * 6 + a;
            unsigned long long v = s_red[srcidx * 33 + col];
            #pragma unroll
            for (int ww = 1; ww < 16; ++ww)
                addf2(v, s_red[(ww * 24 + srcidx) * 33 + col]);

            int yq = 2 * (y0 + r) + (a / 3);   // a 0-2 -> HR row 2y, 3-5 -> 2y+1
            int xq = 2 * (x0 + col);
            int jj = a % 3;
            size_t base = ((size_t)(b * QHH + yq) * QWW + xq) * 3 + jj * 2;
            *(unsigned long long*)(out + base) = v;
        }
    }
}

// ---------------------------------------------------------------------------
extern "C" void kernel_launch(void* const* d_in, const int* in_sizes, int n_in,
                              void* d_out, int out_size)
{
    const float* feat  = (const float*)d_in[0];
    const float* coord = (const float*)d_in[1];
    const float* cell  = (const float*)d_in[2];
    const float* w1    = (const float*)d_in[3];
    const float* b1    = (const float*)d_in[4];
    const float* w2    = (const float*)d_in[5];
    const float* b2    = (const float*)d_in[6];
    float* out = (float*)d_out;

    cudaFuncSetAttribute(metasr_main_kernel,
                         cudaFuncAttributeMaxDynamicSharedMemorySize, SMEM_B);

    mlp_pw_kernel<<<108, 256>>>(coord, cell, w1, b1, w2, b2);
    metasr_main_kernel<<<128, 512, SMEM_B>>>(feat, out);
}